// round 15
// baseline (speedup 1.0000x reference)
#include <cuda_runtime.h>
#include <math.h>
#include <stdint.h>

#define EPSF 1e-8f
#define CR   416                          // rows cached in SMEM (of 512)
#define DYN_SMEM (CR * 128 * 4)           // 212992 B dynamic smem
#define NKS  8                            // fc k-splits
#define GRID_NTM 148                      // persistent: 1 CTA per SM

// Scratch: NKS k-split partials of the FC output (NKS x 512 x 134).
__device__ float g_fcp[NKS * 512 * 134];

__device__ __forceinline__ float softplus_f(float x) {
    return (x > 20.0f) ? x : log1pf(expf(x));
}

#define CPA16(dst_u32, src_ptr) \
    asm volatile("cp.async.cg.shared.global [%0], [%1], 16;" :: "r"(dst_u32), "l"(src_ptr))
#define CPA_COMMIT() asm volatile("cp.async.commit_group;")

// ---------------------------------------------------------------------------
// Kernel 1: FC partials (R11 config: best measured). Grid (64,8), block(136,4).
// ---------------------------------------------------------------------------
__global__ __launch_bounds__(544) void fc_kernel(const float* __restrict__ co,
                                                 const float* __restrict__ W,
                                                 const float* __restrict__ bias) {
    __shared__ __align__(16) float s_co[8 * 128];    // 8 rows x 128 c-chunk
    __shared__ float s_p[4][8][136];                 // partials [cz][row][j]
    const int b0 = blockIdx.x * 8;
    const int ks = blockIdx.y;                       // k-split 0..7
    const int j  = threadIdx.x;                      // 0..135 (active < 134)
    const int cz = threadIdx.y;                      // 0..3
    const int tid = threadIdx.x + threadIdx.y * 136;

    for (int i = tid; i < 1024; i += 544) {
        int r = i >> 7, c = i & 127;
        s_co[r * 128 + c] = co[(size_t)(b0 + r) * 1024 + ks * 128 + c];
    }
    __syncthreads();

    if (j < 134) {
        const float* wp = W + (size_t)(ks * 128) * 134 + j;
        const int c0 = cz * 32;
        float a[8];
#pragma unroll
        for (int r = 0; r < 8; ++r) a[r] = 0.f;
#pragma unroll
        for (int c = c0; c < c0 + 32; ++c) {
            float w = wp[c * 134];
#pragma unroll
            for (int r = 0; r < 8; ++r) a[r] += w * s_co[r * 128 + c];
        }
#pragma unroll
        for (int r = 0; r < 8; ++r) s_p[cz][r][j] = a[r];
    }
    __syncthreads();

    if (cz == 0 && j < 134) {
        float bj = (ks == 0) ? bias[j] : 0.0f;
#pragma unroll
        for (int r = 0; r < 8; ++r) {
            float v = s_p[0][r][j] + s_p[1][r][j] + s_p[2][r][j] + s_p[3][r][j] + bj;
            g_fcp[((size_t)ks * 512 + b0 + r) * 134 + j] = v;
        }
    }
}

// ---------------------------------------------------------------------------
// Block reduction helpers (512 threads = 16 warps).
// ---------------------------------------------------------------------------
__device__ __forceinline__ float block_sum(float v, float* s_red, int wid, int lane) {
#pragma unroll
    for (int o = 16; o; o >>= 1) v += __shfl_xor_sync(0xffffffffu, v, o);
    __syncthreads();
    if (lane == 0) s_red[wid] = v;
    __syncthreads();
    if (wid == 0) {
        float x = (lane < 16) ? s_red[lane] : 0.0f;
#pragma unroll
        for (int o = 8; o; o >>= 1) x += __shfl_xor_sync(0xffffffffu, x, o);
        if (lane == 0) s_red[16] = x;
    }
    __syncthreads();
    return s_red[16];
}

__device__ __forceinline__ float block_max(float v, float* s_red, int wid, int lane) {
#pragma unroll
    for (int o = 16; o; o >>= 1) v = fmaxf(v, __shfl_xor_sync(0xffffffffu, v, o));
    __syncthreads();
    if (lane == 0) s_red[wid] = v;
    __syncthreads();
    if (wid == 0) {
        float x = (lane < 16) ? s_red[lane] : -3.4e38f;
#pragma unroll
        for (int o = 8; o; o >>= 1) x = fmaxf(x, __shfl_xor_sync(0xffffffffu, x, o));
        if (lane == 0) s_red[16] = x;
    }
    __syncthreads();
    return s_red[16];
}

// ---------------------------------------------------------------------------
// Issue one half-slab (13 k-chunks) as 3 cp.async commit groups (4,4,5).
// Each thread copies only its own cells: dst idx == consume idx == (n*32+lane).
// ---------------------------------------------------------------------------
__device__ __forceinline__ void issue_half(const float4* __restrict__ mb4,
                                           unsigned int sbase, int wid, int lane,
                                           int kstart) {
#pragma unroll
    for (int i = 0; i < 4; ++i) {
        const int idx = (wid + 16 * (kstart + i)) * 32 + lane;
        CPA16(sbase + idx * 16, mb4 + idx);
    }
    CPA_COMMIT();
#pragma unroll
    for (int i = 4; i < 8; ++i) {
        const int idx = (wid + 16 * (kstart + i)) * 32 + lane;
        CPA16(sbase + idx * 16, mb4 + idx);
    }
    CPA_COMMIT();
#pragma unroll
    for (int i = 8; i < 13; ++i) {
        const int idx = (wid + 16 * (kstart + i)) * 32 + lane;
        CPA16(sbase + idx * 16, mb4 + idx);
    }
    CPA_COMMIT();
}

// ---------------------------------------------------------------------------
// Consume one chunk: wait until <=WAITN groups pending, cosine logits for
// rows k = K0..K0+CNT-1 of this warp's stride-16 row set (from SMEM cache).
// ---------------------------------------------------------------------------
template <int K0, int CNT, int WAITN>
__device__ __forceinline__ void consume_chunk(const float4* __restrict__ cache4,
                                              const float4 k4, float beta_ink,
                                              float* __restrict__ s_u,
                                              int wid, int lane) {
    asm volatile("cp.async.wait_group %0;" :: "n"(WAITN));
    float d[CNT], q[CNT];
#pragma unroll
    for (int i = 0; i < CNT; ++i) {
        const int n = wid + 16 * (K0 + i);
        float4 v = cache4[n * 32 + lane];
        d[i] = v.x * k4.x + v.y * k4.y + v.z * k4.z + v.w * k4.w;
        q[i] = v.x * v.x + v.y * v.y + v.z * v.z + v.w * v.w;
    }
#pragma unroll
    for (int o = 16; o; o >>= 1) {
#pragma unroll
        for (int i = 0; i < CNT; ++i) {
            d[i] += __shfl_xor_sync(0xffffffffu, d[i], o);
            q[i] += __shfl_xor_sync(0xffffffffu, q[i], o);
        }
    }
    if (lane == 0) {
#pragma unroll
        for (int i = 0; i < CNT; ++i)
            s_u[wid + 16 * (K0 + i)] = beta_ink * d[i] / (sqrtf(q[i]) + EPSF);
    }
}

// ---------------------------------------------------------------------------
// Kernel 2: persistent pipelined NTM head. Grid 148 (1 CTA/SM), 512 threads.
// CTA c handles b = c, c+148, ... (3-4 iterations).
// Per iteration: slab(b) arrives via cp.asyncs issued in the PREVIOUS
// iteration's phase D (half-wise recycling, per-thread cell ownership ->
// no barrier needed), so softmax/read-vec of iteration i overlap the DRAM
// streaming of iteration i+1. Rows: k<13 half1 (SMEM), 13<=k<26 half2 (SMEM),
// k>=26 keep[] regs (plain LDGs issued at iteration start).
// ---------------------------------------------------------------------------
__global__ __launch_bounds__(512, 1) void ntm_kernel(const float* __restrict__ mem,
                                                     const float* __restrict__ prev_w,
                                                     float* __restrict__ d_out) {
    extern __shared__ __align__(16) float s_cache[];     // CR*128 floats
    __shared__ __align__(16) float s_k[128];
    __shared__ float s_raw[8];
    __shared__ float s_scal[8];          // beta, g, s0,s1,s2, gamma, inv_norm_k
    __shared__ float s_w[512];
    __shared__ float s_red[32];
    __shared__ __align__(16) float s_u[2048];   // logits / wg / warp partials

    const int tid  = threadIdx.x;
    const int wid  = tid >> 5;
    const int lane = tid & 31;
    float4* cache4 = (float4*)s_cache;
    const unsigned int sbase = (unsigned int)__cvta_generic_to_shared(s_cache);

    // ---- prologue: start streaming the first slab ----
    {
        const float4* mb4 = (const float4*)mem + (size_t)blockIdx.x * 16384;
        issue_half(mb4, sbase, wid, lane, 0);
        issue_half(mb4, sbase, wid, lane, 13);
    }

    for (int b = blockIdx.x; b < 512; b += GRID_NTM) {
        const float4* mb4 = (const float4*)mem + (size_t)b * 16384;

        // ---- Phase A: sum FC partials -> k + scalar gates (overlaps stream) --
        if (tid < 134) {
            const float* p = g_fcp + (size_t)b * 134 + tid;
            float v = 0.f;
#pragma unroll
            for (int ks = 0; ks < NKS; ++ks) v += p[(size_t)ks * 512 * 134];
            if (tid < 128) s_k[tid] = v;
            else           s_raw[tid - 128] = v;
        }
        __syncthreads();

        if (tid == 0) {
            float beta = softplus_f(s_raw[0]);
            float g = 1.0f / (1.0f + expf(-s_raw[1]));
            float x0 = s_raw[2], x1 = s_raw[3], x2 = s_raw[4];
            float mx = fmaxf(x0, fmaxf(x1, x2));
            float e0 = expf(x0 - mx), e1 = expf(x1 - mx), e2 = expf(x2 - mx);
            float inv = 1.0f / (e0 + e1 + e2);
            s_scal[0] = beta; s_scal[1] = g;
            s_scal[2] = e0 * inv; s_scal[3] = e1 * inv; s_scal[4] = e2 * inv;
            s_scal[5] = 1.0f + softplus_f(s_raw[5]);
        }
        if (wid == 0) {
            float4 kk = ((const float4*)s_k)[lane];
            float ss = kk.x * kk.x + kk.y * kk.y + kk.z * kk.z + kk.w * kk.w;
#pragma unroll
            for (int o = 16; o; o >>= 1) ss += __shfl_xor_sync(0xffffffffu, ss, o);
            if (lane == 0) s_scal[6] = 1.0f / (sqrtf(ss) + EPSF);
        }
        __syncthreads();

        const float beta_ink = s_scal[0] * s_scal[6];     // beta / ||k||
        const float4 k4 = ((const float4*)s_k)[lane];

        // ---- keep-row LDGs for this b (arrive while halves consumed) ----
        float4 keep[6];
#pragma unroll
        for (int i = 0; i < 6; ++i)
            keep[i] = mb4[(wid + 16 * (26 + i)) * 32 + lane];

        // ---- consume half1 (groups 1-3 of 6 pending), then half2 ----
        consume_chunk< 0, 4, 5>(cache4, k4, beta_ink, s_u, wid, lane);
        consume_chunk< 4, 4, 4>(cache4, k4, beta_ink, s_u, wid, lane);
        consume_chunk< 8, 5, 3>(cache4, k4, beta_ink, s_u, wid, lane);
        consume_chunk<13, 4, 2>(cache4, k4, beta_ink, s_u, wid, lane);
        consume_chunk<17, 4, 1>(cache4, k4, beta_ink, s_u, wid, lane);
        consume_chunk<21, 5, 0>(cache4, k4, beta_ink, s_u, wid, lane);

        // ---- keep-row logits ----
        {
            float d[6], q[6];
#pragma unroll
            for (int i = 0; i < 6; ++i) {
                float4 v = keep[i];
                d[i] = v.x * k4.x + v.y * k4.y + v.z * k4.z + v.w * k4.w;
                q[i] = v.x * v.x + v.y * v.y + v.z * v.z + v.w * v.w;
            }
#pragma unroll
            for (int o = 16; o; o >>= 1) {
#pragma unroll
                for (int i = 0; i < 6; ++i) {
                    d[i] += __shfl_xor_sync(0xffffffffu, d[i], o);
                    q[i] += __shfl_xor_sync(0xffffffffu, q[i], o);
                }
            }
            if (lane == 0) {
#pragma unroll
                for (int i = 0; i < 6; ++i)
                    s_u[wid + 16 * (26 + i)] = beta_ink * d[i] / (sqrtf(q[i]) + EPSF);
            }
        }
        __syncthreads();

        // ---- Phase C: softmax over N, gate, shift, sharpen ----
        float logit = s_u[tid];
        float vmax = block_max(logit, s_red, wid, lane);
        float e = expf(logit - vmax);
        float esum = block_sum(e, s_red, wid, lane);
        float w_c = e / esum;

        float g = s_scal[1];
        float wg = g * w_c + (1.0f - g) * prev_w[b * 512 + tid];
        s_u[512 + tid] = wg;
        __syncthreads();

        float ws = s_scal[2] * s_u[512 + ((tid + 511) & 511)]
                 + s_scal[3] * wg
                 + s_scal[4] * s_u[512 + ((tid + 1) & 511)];
        float wp = expf(s_scal[5] * logf(ws));          // ws > 0 always
        float psum = block_sum(wp, s_red, wid, lane);
        float w = wp / (psum + EPSF);
        s_w[tid] = w;
        d_out[512 * 128 + b * 512 + tid] = w;           // output w
        __syncthreads();                                // s_w ready; s_u free

        // ---- Phase D + pipelined prefetch of next slab ----
        const int  bn = b + GRID_NTM;
        const bool has_next = (bn < 512);
        const float4* mn4 = (const float4*)mem + (size_t)bn * 16384;

        float4 acc = make_float4(0.f, 0.f, 0.f, 0.f);
#pragma unroll
        for (int k = 0; k < 13; ++k) {                  // read half1
            const int n = wid + 16 * k;
            float4 v = cache4[n * 32 + lane];
            float wn = s_w[n];
            acc.x += wn * v.x; acc.y += wn * v.y;
            acc.z += wn * v.z; acc.w += wn * v.w;
        }
        if (has_next) issue_half(mn4, sbase, wid, lane, 0);   // recycle half1

#pragma unroll
        for (int k = 13; k < 26; ++k) {                 // read half2
            const int n = wid + 16 * k;
            float4 v = cache4[n * 32 + lane];
            float wn = s_w[n];
            acc.x += wn * v.x; acc.y += wn * v.y;
            acc.z += wn * v.z; acc.w += wn * v.w;
        }
#pragma unroll
        for (int k = 26; k < 32; ++k) {                 // keep rows
            float wn = s_w[wid + 16 * k];
            acc.x += wn * keep[k - 26].x; acc.y += wn * keep[k - 26].y;
            acc.z += wn * keep[k - 26].z; acc.w += wn * keep[k - 26].w;
        }
        if (has_next) issue_half(mn4, sbase, wid, lane, 13);  // recycle half2

        ((float4*)s_u)[wid * 32 + lane] = acc;          // 16 warps x 128 floats
        __syncthreads();

        if (tid < 128) {
            float r = 0.f;
#pragma unroll
            for (int i = 0; i < 16; ++i) r += s_u[i * 128 + tid];
            d_out[b * 128 + tid] = r;                   // output read_vec
        }
        __syncthreads();                                // before s_u/s_k reuse
    }
}

// ---------------------------------------------------------------------------
// Launch.
// ---------------------------------------------------------------------------
extern "C" void kernel_launch(void* const* d_in, const int* in_sizes, int n_in,
                              void* d_out, int out_size) {
    const float* co    = (const float*)d_in[0];   // (512, 1024)
    const float* prevw = (const float*)d_in[1];   // (512, 512)
    const float* mem   = (const float*)d_in[2];   // (512, 512, 128)
    const float* W     = (const float*)d_in[3];   // (1024, 134)
    const float* bias  = (const float*)d_in[4];   // (134,)

    cudaFuncSetAttribute(ntm_kernel, cudaFuncAttributeMaxDynamicSharedMemorySize,
                         DYN_SMEM);

    fc_kernel<<<dim3(64, 8), dim3(136, 4)>>>(co, W, bias);
    ntm_kernel<<<GRID_NTM, 512, DYN_SMEM>>>(mem, prevw, (float*)d_out);
}